// round 2
// baseline (speedup 1.0000x reference)
#include <cuda_runtime.h>
#include <cstdint>

// x: [N=64, C=512, H=56, W=56] fp32. 2:4 structured sparsity along C:
// within each group of 4 channels (same n,h,w), zero the 2 smallest-|x|
// entries (ties: lower channel index dropped first, matching jax top_k).
//
// HBM-bound streaming kernel: each thread handles one 4-channel group at
// 8 consecutive hw positions (2 float4 each of 4 channels = 8 independent
// 16B loads, front-batched for MLP=8). Streaming cache hints (__ldcs/__stcs)
// since every byte is touched exactly once.

static constexpr int N_DIM  = 64;
static constexpr int C_DIM  = 512;
static constexpr int HW     = 56 * 56;          // 3136
static constexpr int HW4    = HW / 4;           // 784 float4 per channel plane
static constexpr int HW8    = HW4 / 2;          // 392 thread-chunks per plane
static constexpr int GROUPS = C_DIM / 4;        // 128
static constexpr long long TOTAL_T = (long long)N_DIM * GROUPS * HW8; // 3,211,264

// keep element i iff at least 2 of the other 3 are "strictly smaller"
// under less(j,i) = (|a_j| < |a_i|) || (|a_j| == |a_i| && j < i).
__device__ __forceinline__ void mask4(float& x0, float& x1, float& x2, float& x3) {
    float a0 = fabsf(x0), a1 = fabsf(x1), a2 = fabsf(x2), a3 = fabsf(x3);
    int r0 = 0, r1 = 0, r2 = 0, r3 = 0;
    if (a0 <= a1) r1++; else r0++;   // less(0,1) = a0<=a1 ; less(1,0) = a1<a0
    if (a0 <= a2) r2++; else r0++;
    if (a0 <= a3) r3++; else r0++;
    if (a1 <= a2) r2++; else r1++;
    if (a1 <= a3) r3++; else r1++;
    if (a2 <= a3) r3++; else r2++;
    x0 = (r0 >= 2) ? x0 : 0.0f;
    x1 = (r1 >= 2) ? x1 : 0.0f;
    x2 = (r2 >= 2) ? x2 : 0.0f;
    x3 = (r3 >= 2) ? x3 : 0.0f;
}

__device__ __forceinline__ void mask4x4(float4& v0, float4& v1, float4& v2, float4& v3) {
    mask4(v0.x, v1.x, v2.x, v3.x);
    mask4(v0.y, v1.y, v2.y, v3.y);
    mask4(v0.z, v1.z, v2.z, v3.z);
    mask4(v0.w, v1.w, v2.w, v3.w);
}

__global__ void __launch_bounds__(256)
sparsity24_kernel(const float4* __restrict__ x4, float4* __restrict__ o4) {
    long long t = (long long)blockIdx.x * blockDim.x + threadIdx.x;
    if (t >= TOTAL_T) return;

    // decode: t -> (n*GROUPS + g, hw8)
    int hw8 = (int)(t % HW8);
    long long ng = t / HW8;            // n*GROUPS + g

    // base float4 index of channel c = g*4, hw4 = hw8*2
    long long base = ng * (4LL * HW4) + (long long)hw8 * 2;

    // 8 independent loads, front-batched for MLP
    float4 a0 = __ldcs(&x4[base]);
    float4 b0 = __ldcs(&x4[base + 1]);
    float4 a1 = __ldcs(&x4[base + HW4]);
    float4 b1 = __ldcs(&x4[base + HW4 + 1]);
    float4 a2 = __ldcs(&x4[base + 2 * HW4]);
    float4 b2 = __ldcs(&x4[base + 2 * HW4 + 1]);
    float4 a3 = __ldcs(&x4[base + 3 * HW4]);
    float4 b3 = __ldcs(&x4[base + 3 * HW4 + 1]);

    mask4x4(a0, a1, a2, a3);
    mask4x4(b0, b1, b2, b3);

    __stcs(&o4[base],               a0);
    __stcs(&o4[base + 1],           b0);
    __stcs(&o4[base + HW4],         a1);
    __stcs(&o4[base + HW4 + 1],     b1);
    __stcs(&o4[base + 2 * HW4],     a2);
    __stcs(&o4[base + 2 * HW4 + 1], b2);
    __stcs(&o4[base + 3 * HW4],     a3);
    __stcs(&o4[base + 3 * HW4 + 1], b3);
}

extern "C" void kernel_launch(void* const* d_in, const int* in_sizes, int n_in,
                              void* d_out, int out_size) {
    const float4* x4 = (const float4*)d_in[0];
    float4* o4 = (float4*)d_out;
    int threads = 256;
    long long blocks = (TOTAL_T + threads - 1) / threads;
    sparsity24_kernel<<<(unsigned)blocks, threads>>>(x4, o4);
}

// round 3
// speedup vs baseline: 1.0751x; 1.0751x over previous
#include <cuda_runtime.h>
#include <cstdint>

// x: [N=64, C=512, H=56, W=56] fp32. 2:4 structured sparsity along C:
// within each group of 4 channels (same n,h,w), zero the 2 smallest-|x|
// entries (ties: lower channel index dropped first, matching jax top_k).
//
// R1 structure (4 float4 loads/thread, regs=32, occ~80%) + streaming
// cache hints only. R2 showed MLP=8/thread kills occupancy (regs 60) and
// regresses; per-thread MLP=4 at 80% occupancy is the sweet spot.

static constexpr int N_DIM  = 64;
static constexpr int C_DIM  = 512;
static constexpr int HW     = 56 * 56;          // 3136
static constexpr int HW4    = HW / 4;           // 784 float4 per channel plane
static constexpr int GROUPS = C_DIM / 4;        // 128
static constexpr long long TOTAL_T = (long long)N_DIM * GROUPS * HW4; // 6,422,528

// keep element i iff at least 2 of the other 3 are "strictly smaller"
// under less(j,i) = (|a_j| < |a_i|) || (|a_j| == |a_i| && j < i).
__device__ __forceinline__ void mask4(float& x0, float& x1, float& x2, float& x3) {
    float a0 = fabsf(x0), a1 = fabsf(x1), a2 = fabsf(x2), a3 = fabsf(x3);
    int r0 = 0, r1 = 0, r2 = 0, r3 = 0;
    if (a0 <= a1) r1++; else r0++;   // less(0,1)=a0<=a1 ; less(1,0)=a1<a0
    if (a0 <= a2) r2++; else r0++;
    if (a0 <= a3) r3++; else r0++;
    if (a1 <= a2) r2++; else r1++;
    if (a1 <= a3) r3++; else r1++;
    if (a2 <= a3) r3++; else r2++;
    x0 = (r0 >= 2) ? x0 : 0.0f;
    x1 = (r1 >= 2) ? x1 : 0.0f;
    x2 = (r2 >= 2) ? x2 : 0.0f;
    x3 = (r3 >= 2) ? x3 : 0.0f;
}

__global__ void __launch_bounds__(256)
sparsity24_kernel(const float4* __restrict__ x4, float4* __restrict__ o4) {
    long long t = (long long)blockIdx.x * blockDim.x + threadIdx.x;
    if (t >= TOTAL_T) return;

    // decode: t -> (n*GROUPS + g, hw4); channel stride = HW4 float4
    int hw4 = (int)(t % HW4);
    long long ng = t / HW4;

    long long base = ng * (4LL * HW4) + hw4;

    float4 v0 = __ldcs(&x4[base]);
    float4 v1 = __ldcs(&x4[base + HW4]);
    float4 v2 = __ldcs(&x4[base + 2 * HW4]);
    float4 v3 = __ldcs(&x4[base + 3 * HW4]);

    mask4(v0.x, v1.x, v2.x, v3.x);
    mask4(v0.y, v1.y, v2.y, v3.y);
    mask4(v0.z, v1.z, v2.z, v3.z);
    mask4(v0.w, v1.w, v2.w, v3.w);

    __stcs(&o4[base],           v0);
    __stcs(&o4[base + HW4],     v1);
    __stcs(&o4[base + 2 * HW4], v2);
    __stcs(&o4[base + 3 * HW4], v3);
}

extern "C" void kernel_launch(void* const* d_in, const int* in_sizes, int n_in,
                              void* d_out, int out_size) {
    const float4* x4 = (const float4*)d_in[0];
    float4* o4 = (float4*)d_out;
    int threads = 256;
    long long blocks = (TOTAL_T + threads - 1) / threads;
    sparsity24_kernel<<<(unsigned)blocks, threads>>>(x4, o4);
}